// round 4
// baseline (speedup 1.0000x reference)
#include <cuda_runtime.h>
#include <math_constants.h>

#define B_   4
#define C_   256
#define H_   64
#define W_   64
#define NROI 128
#define OUTK 7   // 7x7 output bins

// One warp handles one (roi n, channel c): 128*256 = 32768 warps.
// Lanes cover x-offsets inside the roi (slot A: rel_x = lane, slot B: rel_x = 32+lane).
// Bin bounds use exact integer math: hs = (i*roi)/7, he = ((i+1)*roi)/7 — bit-identical
// to the reference's f32 floor(i * fl(roi/7)) because the product is only ever an exact
// integer when 7 | roi, where f32 arithmetic is exact too.
__global__ __launch_bounds__(256) void roi_pool_direct(
    const float* __restrict__ feat,
    const int*   __restrict__ rois,
    float*       __restrict__ out)
{
    __shared__ float colmax[8][OUTK][48];   // [warp][row-bin i][rel_x]

    const int warp = threadIdx.x >> 5;
    const int lane = threadIdx.x & 31;
    const int gw   = blockIdx.x * 8 + warp;     // global warp id = n*256 + c
    const int n    = gw >> 8;
    const int c    = gw & 255;

    const int b  = __ldg(rois + n * 5 + 0);
    const int x1 = __ldg(rois + n * 5 + 1);
    const int y1 = __ldg(rois + n * 5 + 2);
    const int x2 = __ldg(rois + n * 5 + 3);
    const int y2 = __ldg(rois + n * 5 + 4);
    const int rh = y2 - y1 + 1;                 // 5..48
    const int rw = x2 - x1 + 1;                 // 5..48

    const float* base = feat + (((size_t)b * C_ + c) * H_ + y1) * W_ + x1;
    const bool actA = lane < rw;
    const bool actB = (32 + lane) < rw;

    // ---- main loop over roi rows; flush running column-max at each bin edge ----
    float curA = -CUDART_INF_F;
    float curB = -CUDART_INF_F;
    int iy = 0;
    int nextHe = rh / 7;                        // he(0) = (1*rh)/7

    for (int rel = 0; rel < rh; ++rel) {
        while (rel >= nextHe) {                 // finished bin iy (possibly empty)
            colmax[warp][iy][lane] = curA;
            if (lane < 16) colmax[warp][iy][32 + lane] = curB;
            curA = -CUDART_INF_F;
            curB = -CUDART_INF_F;
            ++iy;
            nextHe = ((iy + 1) * rh) / 7;
        }
        float vA = actA ? __ldg(base + rel * W_ + lane)      : -CUDART_INF_F;
        float vB = actB ? __ldg(base + rel * W_ + 32 + lane) : -CUDART_INF_F;
        curA = fmaxf(curA, vA);
        curB = fmaxf(curB, vB);
    }
    // last bin (always bin 6: hs(6) <= rh-1 < he(6) = rh)
    colmax[warp][iy][lane] = curA;
    if (lane < 16) colmax[warp][iy][32 + lane] = curB;

    __syncwarp();

    // ---- epilogue: 32 lanes cover 49 bins (bin = lane, lane+32) ----
    #pragma unroll
    for (int bin = lane; bin < OUTK * OUTK; bin += 32) {
        const int i = bin / OUTK;
        const int j = bin % OUTK;

        const int hsI = (i * rh) / 7;
        const int heI = ((i + 1) * rh) / 7;
        const int wsJ = (j * rw) / 7;
        const int weJ = ((j + 1) * rw) / 7;
        const bool valid = (heI > hsI) && (weJ > wsJ);

        float m = -CUDART_INF_F;
        for (int x = wsJ; x < weJ; ++x)
            m = fmaxf(m, colmax[warp][i][x]);

        out[((size_t)n * C_ + c) * (OUTK * OUTK) + bin] = valid ? m : 0.0f;
    }
}

extern "C" void kernel_launch(void* const* d_in, const int* in_sizes, int n_in,
                              void* d_out, int out_size) {
    const float* features = (const float*)d_in[0];
    const int*   rois     = (const int*)d_in[1];
    float*       out      = (float*)d_out;

    // 32768 warps total, 8 warps per block
    roi_pool_direct<<<NROI * C_ / 8, 256>>>(features, rois, out);
}

// round 5
// speedup vs baseline: 1.4286x; 1.4286x over previous
#include <cuda_runtime.h>
#include <math_constants.h>

#define B_   4
#define C_   256
#define H_   64
#define W_   64
#define NROI 128
#define OUTK 7

// One warp handles one (roi n, channel pair c0..c0+1): 128*128 = 16384 warps.
// Each lane loads a float2 covering absolute columns {2*lane, 2*lane+1} of the
// full 64-wide row — aligned, unmasked. Out-of-roi columns accumulate garbage
// that the epilogue never reads. Bin bounds are exact integer math, proven
// bit-identical to the reference's f32 floor(i * fl(roi/7)).
__global__ __launch_bounds__(256) void roi_pool_v2(
    const float* __restrict__ feat,
    const int*   __restrict__ rois,
    float*       __restrict__ out)
{
    __shared__ float colmax[8][2][OUTK][64];   // [warp][ch][row-bin][abs x]

    const int warp = threadIdx.x >> 5;
    const int lane = threadIdx.x & 31;
    const int gw   = blockIdx.x * 8 + warp;    // gw = n*128 + cpair
    const int n    = gw >> 7;
    const int c0   = (gw & 127) << 1;          // channels c0, c0+1

    const int b  = __ldg(rois + n * 5 + 0);
    const int x1 = __ldg(rois + n * 5 + 1);
    const int y1 = __ldg(rois + n * 5 + 2);
    const int x2 = __ldg(rois + n * 5 + 3);
    const int y2 = __ldg(rois + n * 5 + 4);
    const int rh = y2 - y1 + 1;                // 5..48
    const int rw = x2 - x1 + 1;                // 5..48

    // Row base pointers (256B-aligned); each row = 32 float2 per warp.
    const float2* r0 = (const float2*)(feat + (((size_t)b * C_ + c0) * H_ + y1) * W_) + lane;
    const float2* r1 = r0 + (H_ * W_ / 2);     // next channel plane

    // ---- main: 7 row-bins, contiguous tiling hs(i+1) == he(i) ----
    int hs = 0;
    #pragma unroll
    for (int iy = 0; iy < OUTK; ++iy) {
        const int he = ((iy + 1) * rh) / 7;
        float2 m0 = make_float2(-CUDART_INF_F, -CUDART_INF_F);
        float2 m1 = make_float2(-CUDART_INF_F, -CUDART_INF_F);
        for (int rel = hs; rel < he; ++rel) {
            float2 v0 = __ldg(r0 + rel * 32);
            float2 v1 = __ldg(r1 + rel * 32);
            m0.x = fmaxf(m0.x, v0.x);  m0.y = fmaxf(m0.y, v0.y);
            m1.x = fmaxf(m1.x, v1.x);  m1.y = fmaxf(m1.y, v1.y);
        }
        ((float2*)colmax[warp][0][iy])[lane] = m0;
        ((float2*)colmax[warp][1][iy])[lane] = m1;
        hs = he;
    }
    __syncwarp();

    // ---- epilogue: 32 lanes cover 49 bins per channel ----
    #pragma unroll
    for (int ch = 0; ch < 2; ++ch) {
        const size_t obase = ((size_t)n * C_ + (c0 + ch)) * (OUTK * OUTK);
        #pragma unroll
        for (int bin = lane; bin < OUTK * OUTK; bin += 32) {
            const int i = bin / OUTK;
            const int j = bin % OUTK;

            const int hsI = (i * rh) / 7;
            const int heI = ((i + 1) * rh) / 7;
            const int wsJ = (j * rw) / 7;
            const int weJ = ((j + 1) * rw) / 7;
            const bool valid = (heI > hsI) && (weJ > wsJ);

            float m = -CUDART_INF_F;
            const int xb = x1 + wsJ, xe = x1 + weJ;
            for (int x = xb; x < xe; ++x)
                m = fmaxf(m, colmax[warp][ch][i][x]);

            out[obase + bin] = valid ? m : 0.0f;
        }
    }
}

extern "C" void kernel_launch(void* const* d_in, const int* in_sizes, int n_in,
                              void* d_out, int out_size) {
    const float* features = (const float*)d_in[0];
    const int*   rois     = (const int*)d_in[1];
    float*       out      = (float*)d_out;

    // 16384 warps, 8 per block -> 2048 blocks
    roi_pool_v2<<<NROI * (C_ / 2) / 8, 256>>>(features, rois, out);
}

// round 6
// speedup vs baseline: 1.5453x; 1.0817x over previous
#include <cuda_runtime.h>
#include <math_constants.h>

#define B_   4
#define C_   256
#define H_   64
#define W_   64
#define NROI 128
#define OUTK 7

__device__ __forceinline__ float4 fmax4(float4 a, float4 b) {
    return make_float4(fmaxf(a.x, b.x), fmaxf(a.y, b.y),
                       fmaxf(a.z, b.z), fmaxf(a.w, b.w));
}

// One warp handles (roi n, channel pair c0..c0+1). Split-lane layout:
//   ch = lane>>4 (channel within pair), xi = lane&15 (float4 covering cols 4*xi..4*xi+3).
// Lanes load only if their 128B line intersects the roi's column lines.
// Bin bounds: exact integer math, bit-identical to reference f32 bounds.
__global__ __launch_bounds__(256) void roi_pool_v3(
    const float* __restrict__ feat,
    const int*   __restrict__ rois,
    float*       __restrict__ out)
{
    __shared__ float colmax[8][2][OUTK][64];   // [warp][ch][row-bin][abs col]

    const int warp = threadIdx.x >> 5;
    const int lane = threadIdx.x & 31;
    const int ch   = lane >> 4;                // 0 or 1
    const int xi   = lane & 15;                // float4 index within 64-col row
    const int gw   = blockIdx.x * 8 + warp;    // gw = n*128 + cpair
    const int n    = gw >> 7;
    const int c0   = (gw & 127) << 1;

    const int b  = __ldg(rois + n * 5 + 0);
    const int x1 = __ldg(rois + n * 5 + 1);
    const int y1 = __ldg(rois + n * 5 + 2);
    const int x2 = __ldg(rois + n * 5 + 3);
    const int y2 = __ldg(rois + n * 5 + 4);
    const int rh = y2 - y1 + 1;                // 5..48
    const int rw = x2 - x1 + 1;                // 5..48

    // Line predication: my 128B line is xi>>3 (cols [0,32) or [32,64)).
    const int lineLo = x1 >> 5, lineHi = x2 >> 5;
    const int myline = xi >> 3;
    const bool active = (myline >= lineLo) && (myline <= lineHi);

    // Row pointer for my channel, as float4; row stride = 16 float4.
    const float4* rp = (const float4*)(feat + (((size_t)b * C_ + (c0 + ch)) * H_ + y1) * W_) + xi;

    const float4 NEG4 = make_float4(-CUDART_INF_F, -CUDART_INF_F,
                                    -CUDART_INF_F, -CUDART_INF_F);

    // ---- main: 7 contiguous row-bins, 2 rows per iteration ----
    int hs = 0;
    #pragma unroll
    for (int iy = 0; iy < OUTK; ++iy) {
        const int he = ((iy + 1) * rh) / 7;
        float4 m = NEG4;
        int rel = hs;
        if (active) {
            for (; rel + 2 <= he; rel += 2) {
                float4 a = __ldg(rp + rel * 16);
                float4 c = __ldg(rp + rel * 16 + 16);
                m = fmax4(m, fmax4(a, c));
            }
            if (rel < he)
                m = fmax4(m, __ldg(rp + rel * 16));
            ((float4*)(&colmax[warp][ch][iy][0]))[xi] = m;
        }
        hs = he;
    }
    __syncwarp();

    // ---- epilogue: 32 lanes cover 49 bins per channel ----
    #pragma unroll
    for (int ch2 = 0; ch2 < 2; ++ch2) {
        const size_t obase = ((size_t)n * C_ + (c0 + ch2)) * (OUTK * OUTK);
        #pragma unroll
        for (int bin = lane; bin < OUTK * OUTK; bin += 32) {
            const int i = bin / OUTK;
            const int j = bin % OUTK;

            const int hsI = (i * rh) / 7;
            const int heI = ((i + 1) * rh) / 7;
            const int wsJ = (j * rw) / 7;
            const int weJ = ((j + 1) * rw) / 7;
            const bool valid = (heI > hsI) && (weJ > wsJ);

            float m = -CUDART_INF_F;
            const int xb = x1 + wsJ, xe = x1 + weJ;
            for (int x = xb; x < xe; ++x)
                m = fmaxf(m, colmax[warp][ch2][i][x]);

            out[obase + bin] = valid ? m : 0.0f;
        }
    }
}

extern "C" void kernel_launch(void* const* d_in, const int* in_sizes, int n_in,
                              void* d_out, int out_size) {
    const float* features = (const float*)d_in[0];
    const int*   rois     = (const int*)d_in[1];
    float*       out      = (float*)d_out;

    roi_pool_v3<<<NROI * (C_ / 2) / 8, 256>>>(features, rois, out);
}